// round 2
// baseline (speedup 1.0000x reference)
#include <cuda_runtime.h>
#include <cuda_bf16.h>

// RoIPointPool3d: B=4, N=16384, M=128, C=128, S=512
// Phase 1: per-box ordered compaction of in-box point indices.
//          8 warps x contiguous 2048-pt stripes, sync-free warp-local
//          compaction into smem, single barrier, scan + copy-out.
// Phase 2: warp-per-row gather into (B,M,S,3+C) output + empty flags.

#define BB 4
#define NN 16384
#define MM 128
#define CC 128
#define SS 512
#define ROW (3 + CC)   // 131
#define NWARP 8
#define STRIPE (NN / NWARP)  // 2048

// Scratch (allocation-free per harness rules): index table + clamped counts.
__device__ int g_idx[BB * MM * SS];
__device__ int g_cnt[BB * MM];

__global__ __launch_bounds__(256) void box_select_kernel(
    const float* __restrict__ points,   // (B, N, 3)
    const float* __restrict__ boxes,    // (B, M, 7)
    int B, int N, int M)
{
    const int box = blockIdx.x;         // b*M + m
    const int b = box / M;

    const float* bx = boxes + (size_t)box * 7;
    const float cx = bx[0], cy = bx[1];
    const float dx = bx[3], dy = bx[4], dz = bx[5];
    const float cz = bx[2] + 0.5f * dz;         // bottom center -> geometric center
    const float rz = bx[6];
    const float cosa = cosf(-rz), sina = sinf(-rz);
    const float hx = 0.5f * dx, hy = 0.5f * dy, hz = 0.5f * dz;

    const float* pts = points + (size_t)b * N * 3;

    const int tid  = threadIdx.x;
    const int lane = tid & 31;
    const int wid  = tid >> 5;

    // Per-warp local index lists (capped at SS each: local rank <= global rank,
    // so anything beyond SS locally would be beyond SS globally -> dropped).
    __shared__ int s_idx[NWARP * SS];       // 16 KB
    __shared__ int s_wcnt[NWARP];
    __shared__ int s_woff[NWARP + 1];

    // --- warp-local sync-free ordered compaction over its stripe ---
    {
        const int stripe0 = wid * STRIPE;
        int wcnt = 0;
        for (int it = 0; it < STRIPE / 32; it++) {
            const int i = stripe0 + it * 32 + lane;
            const float x = pts[i * 3 + 0];
            const float y = pts[i * 3 + 1];
            const float z = pts[i * 3 + 2];
            const float sx = x - cx;
            const float sy = y - cy;
            const float lx = sx * cosa - sy * sina;
            const float ly = sx * sina + sy * cosa;
            const bool m = (fabsf(z - cz) <= hz) &&
                           (lx > -hx) && (lx < hx) &&
                           (ly > -hy) && (ly < hy);
            const unsigned bal = __ballot_sync(0xffffffffu, m);
            if (m) {
                const int pos = wcnt + __popc(bal & ((1u << lane) - 1u));
                if (pos < SS) s_idx[wid * SS + pos] = i;
            }
            wcnt += __popc(bal);
        }
        if (lane == 0) s_wcnt[wid] = (wcnt < SS) ? wcnt : SS;
    }
    __syncthreads();

    // --- exclusive scan of 8 warp counts (thread 0) ---
    if (tid == 0) {
        int acc = 0;
        #pragma unroll
        for (int w = 0; w < NWARP; w++) { s_woff[w] = acc; acc += s_wcnt[w]; }
        s_woff[NWARP] = acc;
        g_cnt[box] = (acc < SS) ? acc : SS;
    }
    __syncthreads();

    // --- cooperative copy-out with global cap SS ---
    int* gout = g_idx + box * SS;
    #pragma unroll 1
    for (int w = 0; w < NWARP; w++) {
        const int off = s_woff[w];
        if (off >= SS) break;
        const int n = s_wcnt[w];
        const int lim = (off + n > SS) ? (SS - off) : n;
        for (int k = tid; k < lim; k += 256) {
            gout[off + k] = s_idx[w * SS + k];
        }
    }
}

__global__ __launch_bounds__(256) void gather_kernel(
    const float* __restrict__ points,   // (B, N, 3)
    const float* __restrict__ feats,    // (B, N, C)
    float* __restrict__ out,            // (B, M, S, 3+C)
    float* __restrict__ flag_out,       // (B, M) or nullptr
    int B, int N, int M)
{
    const int warpId = (int)((blockIdx.x * (unsigned)blockDim.x + threadIdx.x) >> 5);
    const int lane = threadIdx.x & 31;
    const int totalRows = B * M * SS;
    if (warpId >= totalRows) return;

    const int box = warpId / SS;
    const int s   = warpId % SS;
    const int b   = box / M;

    const int cnt = g_cnt[box];
    float* o = out + (size_t)warpId * ROW;

    if (flag_out && s == 0 && lane == 0) {
        flag_out[box] = (cnt == 0) ? 1.0f : 0.0f;
    }

    if (cnt == 0) {
        #pragma unroll
        for (int c = lane; c < ROW; c += 32) o[c] = 0.0f;
        return;
    }

    const int idx = g_idx[box * SS + (s % cnt)];
    const float* p = points + ((size_t)b * N + idx) * 3;
    const float* f = feats  + ((size_t)b * N + idx) * CC;

    #pragma unroll
    for (int c = lane; c < ROW; c += 32) {
        o[c] = (c < 3) ? p[c] : f[c - 3];
    }
}

extern "C" void kernel_launch(void* const* d_in, const int* in_sizes, int n_in,
                              void* d_out, int out_size)
{
    const float* points = (const float*)d_in[0];  // (B, N, 3)
    const float* feats  = (const float*)d_in[1];  // (B, N, C)
    const float* boxes  = (const float*)d_in[2];  // (B, M, 7)

    const int N = NN, M = MM;
    const int B = in_sizes[2] / (7 * M);

    // Phase 1: per-box in-box index lists
    box_select_kernel<<<B * M, 256>>>(points, boxes, B, N, M);

    // Phase 2: gather (one warp per output row) + flags
    const long long pooledElems = (long long)B * M * SS * ROW;
    const int nBoxes = B * M;
    float* flag_out = ((long long)out_size >= pooledElems + nBoxes)
                          ? ((float*)d_out + pooledElems) : nullptr;

    const int rows = B * M * SS;
    const int blocks = (rows + 7) / 8;          // 8 warps per 256-thread block
    gather_kernel<<<blocks, 256>>>(points, feats, (float*)d_out, flag_out, B, N, M);
}

// round 3
// speedup vs baseline: 1.0884x; 1.0884x over previous
#include <cuda_runtime.h>
#include <cuda_bf16.h>

// RoIPointPool3d: B=4, N=16384, M=128, C=128, S=512
// Phase 1: per-box ordered compaction of in-box point indices (8 warp-stripes,
//          sync-free warp-local compaction, one barrier, scan + copy-out).
// Phase 2: block-per-box: stage cnt distinct rows in smem, emit 512 rows as
//          float4 stores (output region per box is contiguous & 16B-aligned).

#define BB 4
#define NN 16384
#define MM 128
#define CC 128
#define SS 512
#define ROW (3 + CC)       // 131
#define ROWP 132           // padded smem row stride (floats), 528 B, 16B-divisible
#define MAXR 432           // 432*528 = 228096 B smem (fits < 227 KB limit)
#define NWARP 8
#define STRIPE (NN / NWARP)  // 2048
#define GTHREADS 512

__device__ int g_idx[BB * MM * SS];
__device__ int g_cnt[BB * MM];

__global__ __launch_bounds__(256) void box_select_kernel(
    const float* __restrict__ points,   // (B, N, 3)
    const float* __restrict__ boxes,    // (B, M, 7)
    int B, int N, int M)
{
    const int box = blockIdx.x;
    const int b = box / M;

    const float* bx = boxes + (size_t)box * 7;
    const float cx = bx[0], cy = bx[1];
    const float dx = bx[3], dy = bx[4], dz = bx[5];
    const float cz = bx[2] + 0.5f * dz;
    const float rz = bx[6];
    const float cosa = cosf(-rz), sina = sinf(-rz);
    const float hx = 0.5f * dx, hy = 0.5f * dy, hz = 0.5f * dz;

    const float* pts = points + (size_t)b * N * 3;

    const int tid  = threadIdx.x;
    const int lane = tid & 31;
    const int wid  = tid >> 5;

    __shared__ int s_idx[NWARP * SS];   // 16 KB
    __shared__ int s_wcnt[NWARP];
    __shared__ int s_woff[NWARP + 1];

    {
        const int stripe0 = wid * STRIPE;
        int wcnt = 0;
        for (int it = 0; it < STRIPE / 32; it++) {
            const int i = stripe0 + it * 32 + lane;
            const float x = pts[i * 3 + 0];
            const float y = pts[i * 3 + 1];
            const float z = pts[i * 3 + 2];
            const float sx = x - cx;
            const float sy = y - cy;
            const float lx = sx * cosa - sy * sina;
            const float ly = sx * sina + sy * cosa;
            const bool m = (fabsf(z - cz) <= hz) &&
                           (lx > -hx) && (lx < hx) &&
                           (ly > -hy) && (ly < hy);
            const unsigned bal = __ballot_sync(0xffffffffu, m);
            if (m) {
                const int pos = wcnt + __popc(bal & ((1u << lane) - 1u));
                if (pos < SS) s_idx[wid * SS + pos] = i;
            }
            wcnt += __popc(bal);
        }
        if (lane == 0) s_wcnt[wid] = (wcnt < SS) ? wcnt : SS;
    }
    __syncthreads();

    if (tid == 0) {
        int acc = 0;
        #pragma unroll
        for (int w = 0; w < NWARP; w++) { s_woff[w] = acc; acc += s_wcnt[w]; }
        s_woff[NWARP] = acc;
        g_cnt[box] = (acc < SS) ? acc : SS;
    }
    __syncthreads();

    int* gout = g_idx + box * SS;
    #pragma unroll 1
    for (int w = 0; w < NWARP; w++) {
        const int off = s_woff[w];
        if (off >= SS) break;
        const int n = s_wcnt[w];
        const int lim = (off + n > SS) ? (SS - off) : n;
        for (int k = tid; k < lim; k += 256) {
            gout[off + k] = s_idx[w * SS + k];
        }
    }
}

__global__ __launch_bounds__(GTHREADS) void gather_kernel2(
    const float* __restrict__ points,   // (B, N, 3)
    const float* __restrict__ feats,    // (B, N, C)
    float* __restrict__ out,            // (B, M, S, 3+C)
    float* __restrict__ flag_out,       // (B, M) or nullptr
    int B, int N, int M)
{
    extern __shared__ float sm[];       // MAXR * ROWP floats

    const int box  = blockIdx.x;
    const int b    = box / M;
    const int tid  = threadIdx.x;
    const int lane = tid & 31;
    const int wid  = tid >> 5;
    const int nw   = GTHREADS / 32;

    const int cnt = g_cnt[box];
    float* obox = out + (size_t)box * SS * ROW;

    if (flag_out && tid == 0) flag_out[box] = (cnt == 0) ? 1.0f : 0.0f;

    if (cnt == 0) {
        float4* o4 = (float4*)obox;
        const float4 z4 = make_float4(0.f, 0.f, 0.f, 0.f);
        const int V4 = SS * ROW / 4;    // 16768
        for (int v = tid; v < V4; v += GTHREADS) o4[v] = z4;
        return;
    }

    if (cnt <= MAXR) {
        // --- stage cnt distinct rows into smem (warp per row) ---
        for (int r = wid; r < cnt; r += nw) {
            const int idx = g_idx[box * SS + r];
            const float* p = points + ((size_t)b * N + idx) * 3;
            const float* f = feats  + ((size_t)b * N + idx) * CC;
            float* srow = sm + r * ROWP;
            #pragma unroll
            for (int c = lane; c < ROW; c += 32)
                srow[c] = (c < 3) ? p[c] : f[c - 3];
        }
        __syncthreads();

        // --- emit 512 rows as float4 stores from smem ---
        float4* o4 = (float4*)obox;
        const int V4 = SS * ROW / 4;    // 16768
        for (int v = tid; v < V4; v += GTHREADS) {
            const int flat = v * 4;
            float4 val;
            #pragma unroll
            for (int k = 0; k < 4; k++) {
                const int e = flat + k;
                const int s = e / ROW;          // const-div -> umulhi
                const int c = e - s * ROW;
                const int sr = s % cnt;
                ((float*)&val)[k] = sm[sr * ROWP + c];
            }
            o4[v] = val;
        }
    } else {
        // --- rare fallback: warp per output row, direct from gmem ---
        for (int s = wid; s < SS; s += nw) {
            const int idx = g_idx[box * SS + (s % cnt)];
            const float* p = points + ((size_t)b * N + idx) * 3;
            const float* f = feats  + ((size_t)b * N + idx) * CC;
            float* o = obox + (size_t)s * ROW;
            #pragma unroll
            for (int c = lane; c < ROW; c += 32)
                o[c] = (c < 3) ? p[c] : f[c - 3];
        }
    }
}

extern "C" void kernel_launch(void* const* d_in, const int* in_sizes, int n_in,
                              void* d_out, int out_size)
{
    const float* points = (const float*)d_in[0];  // (B, N, 3)
    const float* feats  = (const float*)d_in[1];  // (B, N, C)
    const float* boxes  = (const float*)d_in[2];  // (B, M, 7)

    const int N = NN, M = MM;
    const int B = in_sizes[2] / (7 * M);

    box_select_kernel<<<B * M, 256>>>(points, boxes, B, N, M);

    const long long pooledElems = (long long)B * M * SS * ROW;
    const int nBoxes = B * M;
    float* flag_out = ((long long)out_size >= pooledElems + nBoxes)
                          ? ((float*)d_out + pooledElems) : nullptr;

    static bool attr_done = false;
    const int smemBytes = MAXR * ROWP * (int)sizeof(float);   // 228096
    if (!attr_done) {
        cudaFuncSetAttribute(gather_kernel2,
                             cudaFuncAttributeMaxDynamicSharedMemorySize, smemBytes);
        attr_done = true;
    }
    gather_kernel2<<<B * M, GTHREADS, smemBytes>>>(points, feats, (float*)d_out,
                                                   flag_out, B, N, M);
}